// round 16
// baseline (speedup 1.0000x reference)
#include <cuda_runtime.h>
#include <cuda_bf16.h>
#include <cuda_fp16.h>
#include <cstdint>
#include <cmath>

// Problem constants
#define BATCH 2
#define SEQ   2048
#define EMB   1024
#define HEADS 16
#define HDIM  64
#define MROWS (BATCH*SEQ)   // 4096

// Scratch (device globals; no allocation allowed)
__device__ __half g_x16[MROWS*EMB];              // x as fp16 (B*T, C)
__device__ __half g_w16[4*EMB*EMB];              // Wq,Wk,Wv,Wo as fp16
__device__ __half g_q16[BATCH*HEADS*SEQ*HDIM];   // (B,H,T,D), pre-scaled by 0.125
__device__ __half g_k16[BATCH*HEADS*SEQ*HDIM];   // (B,H,T,D)
__device__ __half g_v16[BATCH*HEADS*SEQ*HDIM];   // (B,H,D,T)  transposed!
__device__ __half g_a16[MROWS*EMB];              // attention out (B,T,C)

// ---------------------------------------------------------------------------
// PTX helpers (family-level: sm_80+ instructions only)
// ---------------------------------------------------------------------------
__device__ __forceinline__ uint32_t smem_u32(const void* p) {
    uint32_t a;
    asm("{ .reg .u64 t; cvta.to.shared.u64 t, %1; cvt.u32.u64 %0, t; }" : "=r"(a) : "l"(p));
    return a;
}
__device__ __forceinline__ void cp_async16(uint32_t dst, const void* src) {
    asm volatile("cp.async.cg.shared.global [%0], [%1], 16;" :: "r"(dst), "l"(src));
}
__device__ __forceinline__ void cp_commit() {
    asm volatile("cp.async.commit_group;" ::: "memory");
}
template<int N>
__device__ __forceinline__ void cp_wait() {
    asm volatile("cp.async.wait_group %0;" :: "n"(N) : "memory");
}
__device__ __forceinline__ void ldsm_x4(uint32_t* r, uint32_t addr) {
    asm volatile("ldmatrix.sync.aligned.m8n8.x4.shared.b16 {%0,%1,%2,%3}, [%4];"
                 : "=r"(r[0]), "=r"(r[1]), "=r"(r[2]), "=r"(r[3]) : "r"(addr));
}
__device__ __forceinline__ void mma16816h(float* c, const uint32_t* a, const uint32_t* b) {
    asm volatile(
        "mma.sync.aligned.m16n8k16.row.col.f32.f16.f16.f32 "
        "{%0,%1,%2,%3}, {%4,%5,%6,%7}, {%8,%9}, {%0,%1,%2,%3};"
        : "+f"(c[0]), "+f"(c[1]), "+f"(c[2]), "+f"(c[3])
        : "r"(a[0]), "r"(a[1]), "r"(a[2]), "r"(a[3]), "r"(b[0]), "r"(b[1]));
}
// pack two fp32 -> f16x2 (lo in low half)
__device__ __forceinline__ uint32_t pack_h2(float lo, float hi) {
    uint32_t r;
    asm("cvt.rn.f16x2.f32 %0, %1, %2;" : "=r"(r) : "f"(hi), "f"(lo));
    return r;
}
// Swizzle for exact 128B rows (64 fp16). row any, ch 0..7 (16B chunks).
__device__ __forceinline__ uint32_t sw128(int row, int ch) {
    return (uint32_t)(row * 128 + ((ch ^ (row & 7)) * 16));
}

// ---------------------------------------------------------------------------
// Fused fp32 -> fp16 convert, MLP=8.
// ---------------------------------------------------------------------------
#define CVT_BLOCKS 1024     // 512 (x) + 4*128 (weights)

__global__ void __launch_bounds__(256) convert_all_kernel(
    const float* __restrict__ x,
    const float* __restrict__ Wq, const float* __restrict__ Wk,
    const float* __restrict__ Wv, const float* __restrict__ Wo)
{
    const int b = blockIdx.x;
    const int tid = threadIdx.x;
    const float4* src;
    uint2* dst;
    int base;
    if (b < 512) {
        src = (const float4*)x;
        dst = (uint2*)g_x16;
        base = b * 2048;
    } else {
        const int j = b - 512;
        const int w = j >> 7;
        const float* ws = (w == 0) ? Wq : (w == 1) ? Wk : (w == 2) ? Wv : Wo;
        src = (const float4*)ws;
        dst = (uint2*)(g_w16 + (size_t)w * EMB * EMB);
        base = (j & 127) * 2048;
    }
    float4 v[8];
#pragma unroll
    for (int e = 0; e < 8; e++)
        v[e] = src[base + e * 256 + tid];
#pragma unroll
    for (int e = 0; e < 8; e++) {
        uint2 r;
        r.x = pack_h2(v[e].x, v[e].y);
        r.y = pack_h2(v[e].z, v[e].w);
        dst[base + e * 256 + tid] = r;
    }
}

// ---------------------------------------------------------------------------
// fp16 HMMA GEMM: out[m][n] = sum_k A[m][k]*W[n][k] + bias[n].
// CTA: 128x128 tile, 512 threads, 16 warps (4x4), warp tile 32x32.
// BK=64, SW128 swizzled smem, 3 stages x 32KB = 96KB, ~64 regs -> 2 CTAs/SM.
// MODE: 0 = fp32 row-major out; 1 = Q fp16 scaled (B,H,T,D);
//       2 = K fp16 (B,H,T,D);   3 = V fp16 transposed (B,H,D,T)
// ---------------------------------------------------------------------------
#define BK 64
#define TILE_B (128*128)             // 16 KB per operand tile
#define STAGE_B (2*TILE_B)           // 32 KB
#define STAGES 3
#define NCH (EMB/BK)                 // 16
#define GSMEM_BYTES (STAGES*STAGE_B) // 98304
#define GTHREADS 512

template<int MODE>
__device__ __forceinline__ void hgemm_body(
    const __half* __restrict__ A, const __half* __restrict__ B,
    const float* __restrict__ bias, void* __restrict__ dst)
{
    extern __shared__ __half smb[];
    const uint32_t sm0 = smem_u32(smb);

    const int tid  = threadIdx.x;
    const int wid  = tid >> 5;
    const int lane = tid & 31;
    const int m0 = blockIdx.x * 128;
    const int n0 = blockIdx.y * 128;
    const int warp_m = (wid >> 2) * 32;   // 4 warp-rows
    const int warp_n = (wid & 3) * 32;    // 4 warp-cols

    const __half* asrc = A + (size_t)m0 * EMB;
    const __half* bsrc = B + (size_t)n0 * EMB;

    auto load_chunk = [&](int stage, int kc) {
        const uint32_t sb = sm0 + (uint32_t)stage * STAGE_B;
#pragma unroll
        for (int e = 0; e < 2; e++) {
            const int idx = tid * 2 + e;      // 0..1023
            const int row = idx >> 3;
            const int ch  = idx & 7;
            cp_async16(sb + sw128(row, ch),
                       asrc + (size_t)row * EMB + kc * BK + ch * 8);
            cp_async16(sb + TILE_B + sw128(row, ch),
                       bsrc + (size_t)row * EMB + kc * BK + ch * 8);
        }
        cp_commit();
    };

    float c[2][4][4];
#pragma unroll
    for (int mt = 0; mt < 2; mt++)
#pragma unroll
        for (int nt = 0; nt < 4; nt++)
#pragma unroll
            for (int e = 0; e < 4; e++) c[mt][nt][e] = 0.f;

    load_chunk(0, 0);
    load_chunk(1, 1);

    const int lr = lane & 15;
    const int lc = lane >> 4;

    for (int i = 0; i < NCH; i++) {
        if (i < NCH - 1) cp_wait<1>(); else cp_wait<0>();
        __syncthreads();
        if (i + 2 < NCH) load_chunk((i + 2) % STAGES, i + 2);

        const uint32_t ab = sm0 + (uint32_t)(i % STAGES) * STAGE_B;
        const uint32_t bb = ab + TILE_B;

#pragma unroll
        for (int kk = 0; kk < 4; kk++) {
            const int ch = kk * 2 + lc;
            uint32_t fa[2][4], fb[2][4];
#pragma unroll
            for (int mt = 0; mt < 2; mt++)
                ldsm_x4(fa[mt], ab + sw128(warp_m + mt * 16 + lr, ch));
#pragma unroll
            for (int nt2 = 0; nt2 < 2; nt2++)
                ldsm_x4(fb[nt2], bb + sw128(warp_n + nt2 * 16 + lr, ch));
#pragma unroll
            for (int nt2 = 0; nt2 < 2; nt2++) {
                uint32_t b0[2] = {fb[nt2][0], fb[nt2][2]};
                uint32_t b1[2] = {fb[nt2][1], fb[nt2][3]};
#pragma unroll
                for (int mt = 0; mt < 2; mt++) {
                    mma16816h(c[mt][2*nt2],   fa[mt], b0);
                    mma16816h(c[mt][2*nt2+1], fa[mt], b1);
                }
            }
        }
    }

    // --- epilogue (round-11 proven scalar forms)
#pragma unroll
    for (int mt = 0; mt < 2; mt++) {
#pragma unroll
        for (int nt = 0; nt < 4; nt++) {
            const int n = n0 + warp_n + nt * 8 + (lane & 3) * 2;
            const float2 bb2 = *(const float2*)&bias[n];
#pragma unroll
            for (int half = 0; half < 2; half++) {
                const int m = m0 + warp_m + mt * 16 + (lane >> 2) + half * 8;
                float rx = c[mt][nt][half*2+0] + bb2.x;
                float ry = c[mt][nt][half*2+1] + bb2.y;
                if (MODE == 0) {
                    float2 r; r.x = rx; r.y = ry;
                    *(float2*)((float*)dst + (size_t)m * EMB + n) = r;
                } else {
                    const int bh = ((m >> 11) << 4) + (n >> 6);  // b*16 + h
                    const int t  = m & (SEQ - 1);
                    const int d  = n & 63;
                    if (MODE == 1) {
                        __half2 hv;
                        hv.x = __float2half_rn(rx * 0.125f);
                        hv.y = __float2half_rn(ry * 0.125f);
                        *(__half2*)((__half*)dst + ((size_t)bh * SEQ + t) * HDIM + d) = hv;
                    } else if (MODE == 2) {
                        __half2 hv;
                        hv.x = __float2half_rn(rx);
                        hv.y = __float2half_rn(ry);
                        *(__half2*)((__half*)dst + ((size_t)bh * SEQ + t) * HDIM + d) = hv;
                    } else {
                        __half* p = (__half*)dst + ((size_t)bh * HDIM + d) * SEQ + t;
                        p[0]   = __float2half_rn(rx);
                        p[SEQ] = __float2half_rn(ry);
                    }
                }
            }
        }
    }
}

__global__ void __launch_bounds__(GTHREADS, 2) qkv_hgemm_kernel(
    const float* __restrict__ bq, const float* __restrict__ bk, const float* __restrict__ bv)
{
    const int z = blockIdx.z;
    if (z == 0)
        hgemm_body<1>(g_x16, g_w16, bq, g_q16);
    else if (z == 1)
        hgemm_body<2>(g_x16, g_w16 + (size_t)EMB*EMB, bk, g_k16);
    else
        hgemm_body<3>(g_x16, g_w16 + (size_t)2*EMB*EMB, bv, g_v16);
}

__global__ void __launch_bounds__(GTHREADS, 2) proj_hgemm_kernel(
    const float* __restrict__ bo, float* __restrict__ out)
{
    hgemm_body<0>(g_a16, g_w16 + (size_t)3*EMB*EMB, bo, out);
}

// ---------------------------------------------------------------------------
// HMMA causal flash attention, paired-tile softmax.
// CTA: 128 queries x one (b,h). 8 warps, each owns 16 query rows.
// KV tiles of 64 staged in a 4-deep 16KB ring; each loop iteration processes
// TWO tiles (128 KV cols) with ONE online-softmax update. nkv = 2qt+2 (even).
// Warp-uniform skips of fully-masked S/PV blocks in the final (diagonal) pair.
// smem: Q 16K + 4 x 16K = 80K -> 2 CTAs/SM.
// ---------------------------------------------------------------------------
#define Q_BYTES (128*128)            // 16384
#define KV_STAGE_BYTES (2*64*128)    // K + V per stage = 16384
#define KV_STAGES 4
#define ATTN_SMEM (Q_BYTES + KV_STAGES*KV_STAGE_BYTES)   // 81920

__global__ void __launch_bounds__(256, 2) attn_hmma_kernel()
{
    extern __shared__ char smc[];
    const uint32_t sm0 = smem_u32(smc);

    const int tid  = threadIdx.x;
    const int wid  = tid >> 5;
    const int lane = tid & 31;
    const int bh = blockIdx.x;
    const int qt = (gridDim.y - 1) - blockIdx.y;   // heaviest first

    const __half* qg = g_q16 + (size_t)bh * SEQ * HDIM;   // [t][d]
    const __half* kg = g_k16 + (size_t)bh * SEQ * HDIM;   // [t][d]
    const __half* vg = g_v16 + (size_t)bh * HDIM * SEQ;   // [d][t]

    // ---- issue Q tile load (one group)
#pragma unroll
    for (int e = 0; e < 4; e++) {
        const int idx = tid * 4 + e;
        const int row = idx >> 3;
        const int ch  = idx & 7;
        cp_async16(sm0 + sw128(row, ch),
                   qg + ((size_t)qt * 128 + row) * HDIM + ch * 8);
    }
    cp_commit();

    auto load_kv = [&](int stage, int kt) {
        const uint32_t sb = sm0 + Q_BYTES + (uint32_t)stage * KV_STAGE_BYTES;
#pragma unroll
        for (int e = 0; e < 2; e++) {
            const int idx = tid * 2 + e;
            const int row = idx >> 3;
            const int ch  = idx & 7;
            cp_async16(sb + sw128(row, ch),
                       kg + ((size_t)kt * 64 + row) * HDIM + ch * 8);
            cp_async16(sb + 64*128 + sw128(row, ch),
                       vg + (size_t)row * SEQ + kt * 64 + ch * 8);
        }
        cp_commit();
    };

    const int nkv = 2 * qt + 2;      // even, >= 2
    load_kv(0, 0);
    load_kv(1, 1);
    if (nkv > 2) { load_kv(2, 2); load_kv(3, 3); }

    // Q landed when all issued KV groups remain pending
    if (nkv > 2) cp_wait<4>(); else cp_wait<2>();
    __syncthreads();

    const int lr = lane & 15;
    const int lc = lane >> 4;

    // ---- Q fragments (per warp, rows wid*16..+15), 4 k-steps
    uint32_t aq[4][4];
#pragma unroll
    for (int kk = 0; kk < 4; kk++)
        ldsm_x4(aq[kk], sm0 + sw128(wid*16 + lr, kk*2 + lc));

    float o[8][4];
#pragma unroll
    for (int nt = 0; nt < 8; nt++)
#pragma unroll
        for (int e = 0; e < 4; e++) o[nt][e] = 0.f;
    float m0r = -INFINITY, m1r = -INFINITY, l0r = 0.f, l1r = 0.f;

    const float LOG2E = 1.4426950408889634f;
    const int rbase = qt*128 + wid*16 + (lane >> 2);
    const int wmax  = qt*128 + wid*16 + 15;   // warp's max global row

    const int npair = nkv >> 1;
    for (int j = 0; j < npair; j++) {
        const int ta = 2*j, tb = 2*j + 1;
        // pending beyond tile tb after it lands: 2 if more tiles prefetched
        if (nkv - 2*j - 2 >= 2) cp_wait<2>(); else cp_wait<0>();
        __syncthreads();

        const uint32_t sba = sm0 + Q_BYTES + (uint32_t)(ta & 3) * KV_STAGE_BYTES;
        const uint32_t sbb = sm0 + Q_BYTES + (uint32_t)(tb & 3) * KV_STAGE_BYTES;

        // ---- S = Q K^T for both tiles: s[0..7] <- ta, s[8..15] <- tb
        float s[16][4];
#pragma unroll
        for (int nt = 0; nt < 16; nt++)
#pragma unroll
            for (int e = 0; e < 4; e++) s[nt][e] = 0.f;

#pragma unroll
        for (int half = 0; half < 2; half++) {
            const uint32_t kb = half ? sbb : sba;
            const int kt = half ? tb : ta;
#pragma unroll
            for (int nt2 = 0; nt2 < 4; nt2++) {
                if (kt*64 + nt2*16 <= wmax) {    // warp-uniform
#pragma unroll
                    for (int kk = 0; kk < 4; kk++) {
                        uint32_t br[4];
                        ldsm_x4(br, kb + sw128(nt2*16 + lr, kk*2 + lc));
                        uint32_t b0[2] = {br[0], br[2]};
                        uint32_t b1[2] = {br[1], br[3]};
                        mma16816h(s[half*8 + 2*nt2],   aq[kk], b0);
                        mma16816h(s[half*8 + 2*nt2+1], aq[kk], b1);
                    }
                }
            }
        }

        // ---- causal mask (last pair only: cols ta*64 .. ta*64+127)
        if (j == npair - 1) {
#pragma unroll
            for (int nt = 0; nt < 16; nt++) {
                const int col = ta*64 + nt*8 + (lane & 3)*2;
#pragma unroll
                for (int e = 0; e < 4; e++) {
                    const int cc = col + (e & 1);
                    const int rr = rbase + (e >> 1)*8;
                    if (cc > rr) s[nt][e] = -1e30f;
                }
            }
        }

        // ---- single online softmax over 128 cols
        float mx0 = -INFINITY, mx1 = -INFINITY;
#pragma unroll
        for (int nt = 0; nt < 16; nt++) {
            mx0 = fmaxf(mx0, fmaxf(s[nt][0], s[nt][1]));
            mx1 = fmaxf(mx1, fmaxf(s[nt][2], s[nt][3]));
        }
        mx0 = fmaxf(mx0, __shfl_xor_sync(0xffffffffu, mx0, 1));
        mx0 = fmaxf(mx0, __shfl_xor_sync(0xffffffffu, mx0, 2));
        mx1 = fmaxf(mx1, __shfl_xor_sync(0xffffffffu, mx1, 1));
        mx1 = fmaxf(mx1, __shfl_xor_sync(0xffffffffu, mx1, 2));
        const float mn0 = fmaxf(m0r, mx0);
        const float mn1 = fmaxf(m1r, mx1);
        const float a0 = exp2f((m0r - mn0) * LOG2E);
        const float a1 = exp2f((m1r - mn1) * LOG2E);
        m0r = mn0; m1r = mn1;

        float rs0 = 0.f, rs1 = 0.f;
#pragma unroll
        for (int nt = 0; nt < 16; nt++) {
            float p0 = exp2f((s[nt][0] - mn0) * LOG2E);
            float p1 = exp2f((s[nt][1] - mn0) * LOG2E);
            float p2 = exp2f((s[nt][2] - mn1) * LOG2E);
            float p3 = exp2f((s[nt][3] - mn1) * LOG2E);
            s[nt][0] = p0; s[nt][1] = p1; s[nt][2] = p2; s[nt][3] = p3;
            rs0 += p0 + p1; rs1 += p2 + p3;
        }
        rs0 += __shfl_xor_sync(0xffffffffu, rs0, 1);
        rs0 += __shfl_xor_sync(0xffffffffu, rs0, 2);
        rs1 += __shfl_xor_sync(0xffffffffu, rs1, 1);
        rs1 += __shfl_xor_sync(0xffffffffu, rs1, 2);
        l0r = l0r * a0 + rs0;
        l1r = l1r * a1 + rs1;

#pragma unroll
        for (int nt = 0; nt < 8; nt++) {
            o[nt][0] *= a0; o[nt][1] *= a0;
            o[nt][2] *= a1; o[nt][3] *= a1;
        }

        // ---- O += P V for both tiles (skip fully-masked k-groups: P==0)
#pragma unroll
        for (int half = 0; half < 2; half++) {
            const uint32_t vb = (half ? sbb : sba) + 64*128;
            const int kt = half ? tb : ta;
#pragma unroll
            for (int kk = 0; kk < 4; kk++) {
                if (kt*64 + kk*16 <= wmax) {     // warp-uniform
                    const int sb8 = half*8 + 2*kk;
                    uint32_t pf[4];
                    pf[0] = pack_h2(s[sb8][0],   s[sb8][1]);
                    pf[1] = pack_h2(s[sb8][2],   s[sb8][3]);
                    pf[2] = pack_h2(s[sb8+1][0], s[sb8+1][1]);
                    pf[3] = pack_h2(s[sb8+1][2], s[sb8+1][3]);
#pragma unroll
                    for (int nt2 = 0; nt2 < 4; nt2++) {
                        uint32_t br[4];
                        ldsm_x4(br, vb + sw128(nt2*16 + lr, kk*2 + lc));
                        uint32_t b0[2] = {br[0], br[2]};
                        uint32_t b1[2] = {br[1], br[3]};
                        mma16816h(o[2*nt2],   pf, b0);
                        mma16816h(o[2*nt2+1], pf, b1);
                    }
                }
            }
        }

        __syncthreads();   // all warps done with stages (ta&3),(tb&3)
        if (2*j + 4 < nkv) load_kv((2*j + 4) & 3, 2*j + 4);
        if (2*j + 5 < nkv) load_kv((2*j + 5) & 3, 2*j + 5);
    }

    // ---- finalize: write fp16 into (B,T,C)
    const float inv0 = 1.f / l0r;
    const float inv1 = 1.f / l1r;
    const int b = bh >> 4;
    const int h = bh & 15;
    const int t0 = qt*128 + wid*16 + (lane >> 2);
#pragma unroll
    for (int nt = 0; nt < 8; nt++) {
        const int d = nt*8 + (lane & 3)*2;
#pragma unroll
        for (int half = 0; half < 2; half++) {
            const int t = t0 + half*8;
            const float inv = half ? inv1 : inv0;
            const uint32_t hv = pack_h2(o[nt][half*2+0] * inv, o[nt][half*2+1] * inv);
            *(uint32_t*)&g_a16[((size_t)(b*SEQ + t)) * EMB + h*HDIM + d] = hv;
        }
    }
}

// ---------------------------------------------------------------------------
extern "C" void kernel_launch(void* const* d_in, const int* in_sizes, int n_in,
                              void* d_out, int out_size)
{
    const float* x   = (const float*)d_in[0];
    const float* W_q = (const float*)d_in[1];
    const float* b_q = (const float*)d_in[2];
    const float* W_k = (const float*)d_in[3];
    const float* b_k = (const float*)d_in[4];
    const float* W_v = (const float*)d_in[5];
    const float* b_v = (const float*)d_in[6];
    const float* W_o = (const float*)d_in[7];
    const float* b_o = (const float*)d_in[8];
    float* out = (float*)d_out;

    static bool attr_set = false;
    if (!attr_set) {
        cudaFuncSetAttribute(attn_hmma_kernel,
                             cudaFuncAttributeMaxDynamicSharedMemorySize, ATTN_SMEM);
        cudaFuncSetAttribute(qkv_hgemm_kernel,
                             cudaFuncAttributeMaxDynamicSharedMemorySize, GSMEM_BYTES);
        cudaFuncSetAttribute(proj_hgemm_kernel,
                             cudaFuncAttributeMaxDynamicSharedMemorySize, GSMEM_BYTES);
        attr_set = true;
    }

    // 1) fused fp16 conversion (x + 4 weights, one launch, MLP=8)
    convert_all_kernel<<<CVT_BLOCKS, 256>>>(x, W_q, W_k, W_v, W_o);

    // 2) QKV projections (writes fp16 q/k and transposed v)
    dim3 gqkv(MROWS/128, EMB/128, 3);
    qkv_hgemm_kernel<<<gqkv, GTHREADS, GSMEM_BYTES>>>(b_q, b_k, b_v);

    // 3) HMMA flash attention (writes fp16 attention output)
    dim3 gattn(BATCH*HEADS, SEQ/128);
    attn_hmma_kernel<<<gattn, 256, ATTN_SMEM>>>();

    // 4) output projection
    dim3 gproj(MROWS/128, EMB/128);
    proj_hgemm_kernel<<<gproj, GTHREADS, GSMEM_BYTES>>>(b_o, out);
}

// round 17
// speedup vs baseline: 1.0588x; 1.0588x over previous
#include <cuda_runtime.h>
#include <cuda_bf16.h>
#include <cuda_fp16.h>
#include <cstdint>
#include <cmath>

// Problem constants
#define BATCH 2
#define SEQ   2048
#define EMB   1024
#define HEADS 16
#define HDIM  64
#define MROWS (BATCH*SEQ)   // 4096

// Scratch (device globals; no allocation allowed)
__device__ __half g_x16[MROWS*EMB];              // x as fp16 (B*T, C)
__device__ __half g_w16[4*EMB*EMB];              // Wq,Wk,Wv,Wo as fp16
__device__ __half g_q16[BATCH*HEADS*SEQ*HDIM];   // (B,H,T,D), pre-scaled by 0.125
__device__ __half g_k16[BATCH*HEADS*SEQ*HDIM];   // (B,H,T,D)
__device__ __half g_v16[BATCH*HEADS*SEQ*HDIM];   // (B,H,D,T)  transposed!
__device__ __half g_a16[MROWS*EMB];              // attention out (B,T,C)

// ---------------------------------------------------------------------------
// PTX helpers (family-level: sm_80+ instructions only)
// ---------------------------------------------------------------------------
__device__ __forceinline__ uint32_t smem_u32(const void* p) {
    uint32_t a;
    asm("{ .reg .u64 t; cvta.to.shared.u64 t, %1; cvt.u32.u64 %0, t; }" : "=r"(a) : "l"(p));
    return a;
}
__device__ __forceinline__ void cp_async16(uint32_t dst, const void* src) {
    asm volatile("cp.async.cg.shared.global [%0], [%1], 16;" :: "r"(dst), "l"(src));
}
__device__ __forceinline__ void cp_commit() {
    asm volatile("cp.async.commit_group;" ::: "memory");
}
template<int N>
__device__ __forceinline__ void cp_wait() {
    asm volatile("cp.async.wait_group %0;" :: "n"(N) : "memory");
}
__device__ __forceinline__ void ldsm_x4(uint32_t* r, uint32_t addr) {
    asm volatile("ldmatrix.sync.aligned.m8n8.x4.shared.b16 {%0,%1,%2,%3}, [%4];"
                 : "=r"(r[0]), "=r"(r[1]), "=r"(r[2]), "=r"(r[3]) : "r"(addr));
}
__device__ __forceinline__ void mma16816h(float* c, const uint32_t* a, const uint32_t* b) {
    asm volatile(
        "mma.sync.aligned.m16n8k16.row.col.f32.f16.f16.f32 "
        "{%0,%1,%2,%3}, {%4,%5,%6,%7}, {%8,%9}, {%0,%1,%2,%3};"
        : "+f"(c[0]), "+f"(c[1]), "+f"(c[2]), "+f"(c[3])
        : "r"(a[0]), "r"(a[1]), "r"(a[2]), "r"(a[3]), "r"(b[0]), "r"(b[1]));
}
// pack two fp32 -> f16x2 (lo in low half)
__device__ __forceinline__ uint32_t pack_h2(float lo, float hi) {
    uint32_t r;
    asm("cvt.rn.f16x2.f32 %0, %1, %2;" : "=r"(r) : "f"(hi), "f"(lo));
    return r;
}
// Swizzle for exact 128B rows (64 fp16). row any, ch 0..7 (16B chunks).
__device__ __forceinline__ uint32_t sw128(int row, int ch) {
    return (uint32_t)(row * 128 + ((ch ^ (row & 7)) * 16));
}

// ---------------------------------------------------------------------------
// Fused fp32 -> fp16 convert, MLP=8.
// ---------------------------------------------------------------------------
#define CVT_BLOCKS 1024     // 512 (x) + 4*128 (weights)

__global__ void __launch_bounds__(256) convert_all_kernel(
    const float* __restrict__ x,
    const float* __restrict__ Wq, const float* __restrict__ Wk,
    const float* __restrict__ Wv, const float* __restrict__ Wo)
{
    const int b = blockIdx.x;
    const int tid = threadIdx.x;
    const float4* src;
    uint2* dst;
    int base;
    if (b < 512) {
        src = (const float4*)x;
        dst = (uint2*)g_x16;
        base = b * 2048;
    } else {
        const int j = b - 512;
        const int w = j >> 7;
        const float* ws = (w == 0) ? Wq : (w == 1) ? Wk : (w == 2) ? Wv : Wo;
        src = (const float4*)ws;
        dst = (uint2*)(g_w16 + (size_t)w * EMB * EMB);
        base = (j & 127) * 2048;
    }
    float4 v[8];
#pragma unroll
    for (int e = 0; e < 8; e++)
        v[e] = src[base + e * 256 + tid];
#pragma unroll
    for (int e = 0; e < 8; e++) {
        uint2 r;
        r.x = pack_h2(v[e].x, v[e].y);
        r.y = pack_h2(v[e].z, v[e].w);
        dst[base + e * 256 + tid] = r;
    }
}

// ---------------------------------------------------------------------------
// fp16 HMMA GEMM: out[m][n] = sum_k A[m][k]*W[n][k] + bias[n].
// CTA: 128x128 tile, 512 threads, 16 warps (4x4), warp tile 32x32.
// BK=64, SW128 swizzled smem, 3 stages x 32KB = 96KB, ~64 regs -> 2 CTAs/SM.
// MODE: 0 = fp32 row-major out; 1 = Q fp16 scaled (B,H,T,D);
//       2 = K fp16 (B,H,T,D);   3 = V fp16 transposed (B,H,D,T)
// ---------------------------------------------------------------------------
#define BK 64
#define TILE_B (128*128)             // 16 KB per operand tile
#define STAGE_B (2*TILE_B)           // 32 KB
#define STAGES 3
#define NCH (EMB/BK)                 // 16
#define GSMEM_BYTES (STAGES*STAGE_B) // 98304
#define GTHREADS 512

template<int MODE>
__device__ __forceinline__ void hgemm_body(
    const __half* __restrict__ A, const __half* __restrict__ B,
    const float* __restrict__ bias, void* __restrict__ dst)
{
    extern __shared__ __half smb[];
    const uint32_t sm0 = smem_u32(smb);

    const int tid  = threadIdx.x;
    const int wid  = tid >> 5;
    const int lane = tid & 31;
    const int m0 = blockIdx.x * 128;
    const int n0 = blockIdx.y * 128;
    const int warp_m = (wid >> 2) * 32;   // 4 warp-rows
    const int warp_n = (wid & 3) * 32;    // 4 warp-cols

    const __half* asrc = A + (size_t)m0 * EMB;
    const __half* bsrc = B + (size_t)n0 * EMB;

    auto load_chunk = [&](int stage, int kc) {
        const uint32_t sb = sm0 + (uint32_t)stage * STAGE_B;
#pragma unroll
        for (int e = 0; e < 2; e++) {
            const int idx = tid * 2 + e;      // 0..1023
            const int row = idx >> 3;
            const int ch  = idx & 7;
            cp_async16(sb + sw128(row, ch),
                       asrc + (size_t)row * EMB + kc * BK + ch * 8);
            cp_async16(sb + TILE_B + sw128(row, ch),
                       bsrc + (size_t)row * EMB + kc * BK + ch * 8);
        }
        cp_commit();
    };

    float c[2][4][4];
#pragma unroll
    for (int mt = 0; mt < 2; mt++)
#pragma unroll
        for (int nt = 0; nt < 4; nt++)
#pragma unroll
            for (int e = 0; e < 4; e++) c[mt][nt][e] = 0.f;

    load_chunk(0, 0);
    load_chunk(1, 1);

    const int lr = lane & 15;
    const int lc = lane >> 4;

    for (int i = 0; i < NCH; i++) {
        if (i < NCH - 1) cp_wait<1>(); else cp_wait<0>();
        __syncthreads();
        if (i + 2 < NCH) load_chunk((i + 2) % STAGES, i + 2);

        const uint32_t ab = sm0 + (uint32_t)(i % STAGES) * STAGE_B;
        const uint32_t bb = ab + TILE_B;

#pragma unroll
        for (int kk = 0; kk < 4; kk++) {
            const int ch = kk * 2 + lc;
            uint32_t fa[2][4], fb[2][4];
#pragma unroll
            for (int mt = 0; mt < 2; mt++)
                ldsm_x4(fa[mt], ab + sw128(warp_m + mt * 16 + lr, ch));
#pragma unroll
            for (int nt2 = 0; nt2 < 2; nt2++)
                ldsm_x4(fb[nt2], bb + sw128(warp_n + nt2 * 16 + lr, ch));
#pragma unroll
            for (int nt2 = 0; nt2 < 2; nt2++) {
                uint32_t b0[2] = {fb[nt2][0], fb[nt2][2]};
                uint32_t b1[2] = {fb[nt2][1], fb[nt2][3]};
#pragma unroll
                for (int mt = 0; mt < 2; mt++) {
                    mma16816h(c[mt][2*nt2],   fa[mt], b0);
                    mma16816h(c[mt][2*nt2+1], fa[mt], b1);
                }
            }
        }
    }

    // --- epilogue (proven scalar forms)
#pragma unroll
    for (int mt = 0; mt < 2; mt++) {
#pragma unroll
        for (int nt = 0; nt < 4; nt++) {
            const int n = n0 + warp_n + nt * 8 + (lane & 3) * 2;
            const float2 bb2 = *(const float2*)&bias[n];
#pragma unroll
            for (int half = 0; half < 2; half++) {
                const int m = m0 + warp_m + mt * 16 + (lane >> 2) + half * 8;
                float rx = c[mt][nt][half*2+0] + bb2.x;
                float ry = c[mt][nt][half*2+1] + bb2.y;
                if (MODE == 0) {
                    float2 r; r.x = rx; r.y = ry;
                    *(float2*)((float*)dst + (size_t)m * EMB + n) = r;
                } else {
                    const int bh = ((m >> 11) << 4) + (n >> 6);  // b*16 + h
                    const int t  = m & (SEQ - 1);
                    const int d  = n & 63;
                    if (MODE == 1) {
                        __half2 hv;
                        hv.x = __float2half_rn(rx * 0.125f);
                        hv.y = __float2half_rn(ry * 0.125f);
                        *(__half2*)((__half*)dst + ((size_t)bh * SEQ + t) * HDIM + d) = hv;
                    } else if (MODE == 2) {
                        __half2 hv;
                        hv.x = __float2half_rn(rx);
                        hv.y = __float2half_rn(ry);
                        *(__half2*)((__half*)dst + ((size_t)bh * SEQ + t) * HDIM + d) = hv;
                    } else {
                        __half* p = (__half*)dst + ((size_t)bh * HDIM + d) * SEQ + t;
                        p[0]   = __float2half_rn(rx);
                        p[SEQ] = __float2half_rn(ry);
                    }
                }
            }
        }
    }
}

__global__ void __launch_bounds__(GTHREADS, 2) qkv_hgemm_kernel(
    const float* __restrict__ bq, const float* __restrict__ bk, const float* __restrict__ bv)
{
    const int z = blockIdx.z;
    if (z == 0)
        hgemm_body<1>(g_x16, g_w16, bq, g_q16);
    else if (z == 1)
        hgemm_body<2>(g_x16, g_w16 + (size_t)EMB*EMB, bk, g_k16);
    else
        hgemm_body<3>(g_x16, g_w16 + (size_t)2*EMB*EMB, bv, g_v16);
}

__global__ void __launch_bounds__(GTHREADS, 2) proj_hgemm_kernel(
    const float* __restrict__ bo, float* __restrict__ out)
{
    hgemm_body<0>(g_a16, g_w16 + (size_t)3*EMB*EMB, bo, out);
}

// ---------------------------------------------------------------------------
// HMMA causal flash attention, all-fp16 operands, fp32 accum.
// CTA: 128 queries x one (b,h). 8 warps, each owns 16 query rows.
// KV tiles of 64, 3-stage cp.async ring, single sync per iteration.
// smem: Q 16K + 3 x 16K = 64K -> 2 CTAs/SM.   (round-11 optimum, verbatim)
// ---------------------------------------------------------------------------
#define Q_BYTES (128*128)            // 16384
#define KV_STAGE_BYTES (2*64*128)    // K + V per stage = 16384
#define KV_STAGES 3
#define ATTN_SMEM (Q_BYTES + KV_STAGES*KV_STAGE_BYTES)   // 65536

__global__ void __launch_bounds__(256, 2) attn_hmma_kernel()
{
    extern __shared__ char smc[];
    const uint32_t sm0 = smem_u32(smc);

    const int tid  = threadIdx.x;
    const int wid  = tid >> 5;
    const int lane = tid & 31;
    const int bh = blockIdx.x;
    const int qt = (gridDim.y - 1) - blockIdx.y;   // heaviest first

    const __half* qg = g_q16 + (size_t)bh * SEQ * HDIM;   // [t][d]
    const __half* kg = g_k16 + (size_t)bh * SEQ * HDIM;   // [t][d]
    const __half* vg = g_v16 + (size_t)bh * HDIM * SEQ;   // [d][t]

#pragma unroll
    for (int e = 0; e < 4; e++) {
        const int idx = tid * 4 + e;
        const int row = idx >> 3;
        const int ch  = idx & 7;
        cp_async16(sm0 + sw128(row, ch),
                   qg + ((size_t)qt * 128 + row) * HDIM + ch * 8);
    }
    cp_commit();

    auto load_kv = [&](int stage, int kt) {
        const uint32_t sb = sm0 + Q_BYTES + (uint32_t)stage * KV_STAGE_BYTES;
#pragma unroll
        for (int e = 0; e < 2; e++) {
            const int idx = tid * 2 + e;
            const int row = idx >> 3;
            const int ch  = idx & 7;
            cp_async16(sb + sw128(row, ch),
                       kg + ((size_t)kt * 64 + row) * HDIM + ch * 8);
            cp_async16(sb + 64*128 + sw128(row, ch),
                       vg + (size_t)row * SEQ + kt * 64 + ch * 8);
        }
        cp_commit();
    };

    const int nkv = 2 * qt + 2;
    load_kv(0, 0);
    if (nkv > 1) load_kv(1, 1);

    cp_wait<2>();
    __syncthreads();

    const int lr = lane & 15;
    const int lc = lane >> 4;

    uint32_t aq[4][4];
#pragma unroll
    for (int kk = 0; kk < 4; kk++)
        ldsm_x4(aq[kk], sm0 + sw128(wid*16 + lr, kk*2 + lc));

    float o[8][4];
#pragma unroll
    for (int nt = 0; nt < 8; nt++)
#pragma unroll
        for (int e = 0; e < 4; e++) o[nt][e] = 0.f;
    float m0r = -INFINITY, m1r = -INFINITY, l0r = 0.f, l1r = 0.f;

    const float LOG2E = 1.4426950408889634f;
    const int rbase = qt*128 + wid*16 + (lane >> 2);

    for (int kt = 0; kt < nkv; kt++) {
        if (kt < nkv - 1) cp_wait<1>(); else cp_wait<0>();
        __syncthreads();
        if (kt + 2 < nkv) load_kv((kt + 2) % KV_STAGES, kt + 2);

        const uint32_t kb = sm0 + Q_BYTES + (uint32_t)(kt % KV_STAGES) * KV_STAGE_BYTES;
        const uint32_t vb = kb + 64*128;

        float s[8][4];
#pragma unroll
        for (int nt = 0; nt < 8; nt++)
#pragma unroll
            for (int e = 0; e < 4; e++) s[nt][e] = 0.f;

#pragma unroll
        for (int kk = 0; kk < 4; kk++) {
#pragma unroll
            for (int nt2 = 0; nt2 < 4; nt2++) {
                uint32_t br[4];
                ldsm_x4(br, kb + sw128(nt2*16 + lr, kk*2 + lc));
                uint32_t b0[2] = {br[0], br[2]};
                uint32_t b1[2] = {br[1], br[3]};
                mma16816h(s[2*nt2],   aq[kk], b0);
                mma16816h(s[2*nt2+1], aq[kk], b1);
            }
        }

        if (kt >= 2*qt) {
#pragma unroll
            for (int nt = 0; nt < 8; nt++) {
                const int col = kt*64 + nt*8 + (lane & 3)*2;
#pragma unroll
                for (int e = 0; e < 4; e++) {
                    const int cc = col + (e & 1);
                    const int rr = rbase + (e >> 1)*8;
                    if (cc > rr) s[nt][e] = -1e30f;
                }
            }
        }

        float mx0 = -INFINITY, mx1 = -INFINITY;
#pragma unroll
        for (int nt = 0; nt < 8; nt++) {
            mx0 = fmaxf(mx0, fmaxf(s[nt][0], s[nt][1]));
            mx1 = fmaxf(mx1, fmaxf(s[nt][2], s[nt][3]));
        }
        mx0 = fmaxf(mx0, __shfl_xor_sync(0xffffffffu, mx0, 1));
        mx0 = fmaxf(mx0, __shfl_xor_sync(0xffffffffu, mx0, 2));
        mx1 = fmaxf(mx1, __shfl_xor_sync(0xffffffffu, mx1, 1));
        mx1 = fmaxf(mx1, __shfl_xor_sync(0xffffffffu, mx1, 2));
        const float mn0 = fmaxf(m0r, mx0);
        const float mn1 = fmaxf(m1r, mx1);
        const float a0 = exp2f((m0r - mn0) * LOG2E);
        const float a1 = exp2f((m1r - mn1) * LOG2E);
        m0r = mn0; m1r = mn1;

        float rs0 = 0.f, rs1 = 0.f;
#pragma unroll
        for (int nt = 0; nt < 8; nt++) {
            float p0 = exp2f((s[nt][0] - mn0) * LOG2E);
            float p1 = exp2f((s[nt][1] - mn0) * LOG2E);
            float p2 = exp2f((s[nt][2] - mn1) * LOG2E);
            float p3 = exp2f((s[nt][3] - mn1) * LOG2E);
            s[nt][0] = p0; s[nt][1] = p1; s[nt][2] = p2; s[nt][3] = p3;
            rs0 += p0 + p1; rs1 += p2 + p3;
        }
        rs0 += __shfl_xor_sync(0xffffffffu, rs0, 1);
        rs0 += __shfl_xor_sync(0xffffffffu, rs0, 2);
        rs1 += __shfl_xor_sync(0xffffffffu, rs1, 1);
        rs1 += __shfl_xor_sync(0xffffffffu, rs1, 2);
        l0r = l0r * a0 + rs0;
        l1r = l1r * a1 + rs1;

#pragma unroll
        for (int nt = 0; nt < 8; nt++) {
            o[nt][0] *= a0; o[nt][1] *= a0;
            o[nt][2] *= a1; o[nt][3] *= a1;
        }

        uint32_t pf[4][4];
#pragma unroll
        for (int kk = 0; kk < 4; kk++) {
            pf[kk][0] = pack_h2(s[2*kk][0],   s[2*kk][1]);
            pf[kk][1] = pack_h2(s[2*kk][2],   s[2*kk][3]);
            pf[kk][2] = pack_h2(s[2*kk+1][0], s[2*kk+1][1]);
            pf[kk][3] = pack_h2(s[2*kk+1][2], s[2*kk+1][3]);
        }

#pragma unroll
        for (int kk = 0; kk < 4; kk++) {
#pragma unroll
            for (int nt2 = 0; nt2 < 4; nt2++) {
                uint32_t br[4];
                ldsm_x4(br, vb + sw128(nt2*16 + lr, kk*2 + lc));
                uint32_t b0[2] = {br[0], br[2]};
                uint32_t b1[2] = {br[1], br[3]};
                mma16816h(o[2*nt2],   pf[kk], b0);
                mma16816h(o[2*nt2+1], pf[kk], b1);
            }
        }
    }

    const float inv0 = 1.f / l0r;
    const float inv1 = 1.f / l1r;
    const int b = bh >> 4;
    const int h = bh & 15;
    const int t0 = qt*128 + wid*16 + (lane >> 2);
#pragma unroll
    for (int nt = 0; nt < 8; nt++) {
        const int d = nt*8 + (lane & 3)*2;
#pragma unroll
        for (int half = 0; half < 2; half++) {
            const int t = t0 + half*8;
            const float inv = half ? inv1 : inv0;
            const uint32_t hv = pack_h2(o[nt][half*2+0] * inv, o[nt][half*2+1] * inv);
            *(uint32_t*)&g_a16[((size_t)(b*SEQ + t)) * EMB + h*HDIM + d] = hv;
        }
    }
}

// ---------------------------------------------------------------------------
extern "C" void kernel_launch(void* const* d_in, const int* in_sizes, int n_in,
                              void* d_out, int out_size)
{
    const float* x   = (const float*)d_in[0];
    const float* W_q = (const float*)d_in[1];
    const float* b_q = (const float*)d_in[2];
    const float* W_k = (const float*)d_in[3];
    const float* b_k = (const float*)d_in[4];
    const float* W_v = (const float*)d_in[5];
    const float* b_v = (const float*)d_in[6];
    const float* W_o = (const float*)d_in[7];
    const float* b_o = (const float*)d_in[8];
    float* out = (float*)d_out;

    static bool attr_set = false;
    if (!attr_set) {
        cudaFuncSetAttribute(attn_hmma_kernel,
                             cudaFuncAttributeMaxDynamicSharedMemorySize, ATTN_SMEM);
        cudaFuncSetAttribute(qkv_hgemm_kernel,
                             cudaFuncAttributeMaxDynamicSharedMemorySize, GSMEM_BYTES);
        cudaFuncSetAttribute(proj_hgemm_kernel,
                             cudaFuncAttributeMaxDynamicSharedMemorySize, GSMEM_BYTES);
        attr_set = true;
    }

    // 1) fused fp16 conversion (x + 4 weights, one launch, MLP=8)
    convert_all_kernel<<<CVT_BLOCKS, 256>>>(x, W_q, W_k, W_v, W_o);

    // 2) QKV projections (writes fp16 q/k and transposed v)
    dim3 gqkv(MROWS/128, EMB/128, 3);
    qkv_hgemm_kernel<<<gqkv, GTHREADS, GSMEM_BYTES>>>(b_q, b_k, b_v);

    // 3) HMMA flash attention (writes fp16 attention output)
    dim3 gattn(BATCH*HEADS, SEQ/128);
    attn_hmma_kernel<<<gattn, 256, ATTN_SMEM>>>();

    // 4) output projection
    dim3 gproj(MROWS/128, EMB/128);
    proj_hgemm_kernel<<<gproj, GTHREADS, GSMEM_BYTES>>>(b_o, out);
}